// round 13
// baseline (speedup 1.0000x reference)
#include <cuda_runtime.h>

#define NB 64
#define NP 24564
#define NM 16
#define NC 21

#define MROWS 256
#define MGX ((NP + MROWS - 1) / MROWS)   // 96

#define SBLK 1024
#define NV 24
#define CAP 2048

// -------- scratch (no allocations allowed; zero-initialized at load,
// re-zeroed by the last k_selfix block each run) --------
__device__ float g_mined[(size_t)NB * NP];
__device__ unsigned long long g_bpkey[NB * NM];
__device__ int g_numpos[NB];
__device__ float g_sumpos[NB];
__device__ float g_lossl;
__device__ float g_lossc;
__device__ unsigned g_done;

__device__ __forceinline__ float sl1_sum(float tx1, float ty1, float tx2, float ty2,
                                         float px, float py, float pw, float ph,
                                         float4 ld)
{
    float lt0 = ((tx1 + tx2) * 0.5f - px) / (0.1f * pw);
    float lt1 = ((ty1 + ty2) * 0.5f - py) / (0.1f * ph);
    float lt2 = __logf((tx2 - tx1) / pw) / 0.2f;
    float lt3 = __logf((ty2 - ty1) / ph) / 0.2f;
    float s = 0.f, d, a;
    d = ld.x - lt0; a = fabsf(d); s += (a < 1.f) ? 0.5f * d * d : a - 0.5f;
    d = ld.y - lt1; a = fabsf(d); s += (a < 1.f) ? 0.5f * d * d : a - 0.5f;
    d = ld.z - lt2; a = fabsf(d); s += (a < 1.f) ? 0.5f * d * d : a - 0.5f;
    d = ld.w - lt3; a = fabsf(d); s += (a < 1.f) ? 0.5f * d * d : a - 0.5f;
    return s;
}

// Fused: stream conf (lse), IoU matching, positive accumulation, mined write.
__global__ void __launch_bounds__(MROWS) k_main(const float* __restrict__ loc,
                                                const float* __restrict__ conf,
                                                const float* __restrict__ priors,
                                                const float* __restrict__ targets)
{
    int b = blockIdx.y;
    int r0 = blockIdx.x * MROWS;
    int rows = NP - r0; if (rows > MROWS) rows = MROWS;
    int tid = threadIdx.x, lane = tid & 31;

    __shared__ float s_conf[MROWS * NC];      // 21504 B
    __shared__ float s_t[NM][6];
    __shared__ unsigned long long s_key[NM];
    __shared__ float s_lossl, s_sumpos;
    __shared__ int s_np;

    if (tid < NM) {
        const float* tg = targets + ((size_t)b * NM + tid) * 5;
        float x1 = tg[0], y1 = tg[1], x2 = tg[2], y2 = tg[3];
        s_t[tid][0] = x1; s_t[tid][1] = y1; s_t[tid][2] = x2; s_t[tid][3] = y2;
        s_t[tid][4] = (x2 - x1) * (y2 - y1);
        s_t[tid][5] = tg[4];
        s_key[tid] = 0ull;
    }
    if (tid == 0) { s_lossl = 0.f; s_sumpos = 0.f; s_np = 0; }

    // stage conf rows [r0, r0+rows) coalesced (rows*NC divisible by 4: 256*21, 244*21)
    {
        int n4 = (rows * NC) >> 2;
        const float4* src = (const float4*)conf + ((((size_t)b * NP + r0) * NC) >> 2);
        float4* s4 = (float4*)s_conf;
        for (int i = tid; i < n4; i += MROWS) s4[i] = __ldg(src + i);
    }
    __syncthreads();

    float iou_arr[NM];
    float t_lossl = 0.f, t_sumpos = 0.f;
    int t_np = 0;
    bool act = (tid < rows);
    int p = r0 + tid;

    if (act) {
        float4 pr = __ldg((const float4*)priors + p);
        float bx1 = pr.x - pr.z * 0.5f;
        float by1 = pr.y - pr.w * 0.5f;
        float bx2 = pr.x + pr.z * 0.5f;
        float by2 = pr.y + pr.w * 0.5f;
        float area_b = (bx2 - bx1) * (by2 - by1);

        float bov = -1.f;
        int bj = 0;
#pragma unroll
        for (int j = 0; j < NM; j++) {
            float ix1 = fmaxf(s_t[j][0], bx1);
            float iy1 = fmaxf(s_t[j][1], by1);
            float ix2 = fminf(s_t[j][2], bx2);
            float iy2 = fminf(s_t[j][3], by2);
            float iw = fmaxf(ix2 - ix1, 0.f);
            float ih = fmaxf(iy2 - iy1, 0.f);
            float inter = iw * ih;
            float iou = __fdividef(inter, s_t[j][4] + area_b - inter);
            iou_arr[j] = iou;
            if (iou > bov) { bov = iou; bj = j; }          // first-max over j
        }

        int cf = 0;
        bool pos = false;
        if (!(bov < 0.5f)) { cf = (int)(s_t[bj][5] + 1.0f); pos = true; }

        const float* row = s_conf + tid * NC;
        float e0 = 0.f, e1 = 0.f, e2 = 0.f;
#pragma unroll
        for (int c = 0; c < NC; c += 3) {
            e0 += __expf(row[c]);
            if (c + 1 < NC) e1 += __expf(row[c + 1]);
            if (c + 2 < NC) e2 += __expf(row[c + 2]);
        }
        float lca = __logf(e0 + e1 + e2) - row[cf];

        size_t off = (size_t)b * NP + p;
        if (pos) {
            float4 ld = __ldg((const float4*)loc + off);
            t_lossl += sl1_sum(s_t[bj][0], s_t[bj][1], s_t[bj][2], s_t[bj][3],
                               pr.x, pr.y, pr.z, pr.w, ld);
            t_sumpos += lca;
            t_np = 1;
            g_mined[off] = 0.f;
        } else {
            g_mined[off] = lca;
        }
    } else {
#pragma unroll
        for (int j = 0; j < NM; j++) iou_arr[j] = -1.f;
    }

    // per-truth best prior: packed (ov, ~p) warp max then smem atomicMax
#pragma unroll
    for (int j = 0; j < NM; j++) {
        unsigned long long key = 0ull;
        if (act && iou_arr[j] >= 0.f)
            key = ((unsigned long long)__float_as_uint(iou_arr[j]) << 32) |
                  (unsigned long long)(0xFFFFFFFFu - (unsigned)p);
#pragma unroll
        for (int o = 16; o > 0; o >>= 1) {
            unsigned long long other = __shfl_down_sync(0xFFFFFFFFu, key, o);
            if (other > key) key = other;
        }
        if (lane == 0 && key) atomicMax(&s_key[j], key);
    }
    // block loss sums
#pragma unroll
    for (int o = 16; o > 0; o >>= 1) {
        t_lossl += __shfl_down_sync(0xFFFFFFFFu, t_lossl, o);
        t_sumpos += __shfl_down_sync(0xFFFFFFFFu, t_sumpos, o);
        t_np += __shfl_down_sync(0xFFFFFFFFu, t_np, o);
    }
    if (lane == 0) {
        atomicAdd(&s_lossl, t_lossl);
        atomicAdd(&s_sumpos, t_sumpos);
        atomicAdd(&s_np, t_np);
    }
    __syncthreads();

    if (tid < NM && s_key[tid]) atomicMax(&g_bpkey[b * NM + tid], s_key[tid]);
    if (tid == 0) {
        atomicAdd(&g_lossl, s_lossl);
        atomicAdd(&g_sumpos[b], s_sumpos);
        atomicAdd(&g_numpos[b], s_np);
    }
}

// Fused: override fixup + radix select (2 full passes, then candidate-compacted
// passes) + final output + state reset by the last block.
__global__ void __launch_bounds__(SBLK) k_selfix(const float* __restrict__ loc,
                                                 const float* __restrict__ conf,
                                                 const float* __restrict__ priors,
                                                 const float* __restrict__ targets,
                                                 float* __restrict__ out)
{
    int b = blockIdx.x;
    int tid = threadIdx.x;
    int lane = tid & 31, w = tid >> 5;

    __shared__ unsigned hist[32 * 257];          // 32896 B, per-warp padded
    __shared__ unsigned s_ssum[256];
    __shared__ unsigned s_cand[CAP];             // 8192 B
    __shared__ float s_cr[NM][NC];
    __shared__ float s_sl[NM][NM];
    __shared__ float s_lse[NM], s_lcanew[NM];
    __shared__ float s_tt[NM][6];
    __shared__ int s_p[NM], s_cnew[NM], s_cold0[NM], s_bt0[NM], s_pos0[NM], s_zero[NM];
    __shared__ int s_K, s_last;
    __shared__ float s_base;
    __shared__ unsigned s_prefix, s_krem, s_cgt, s_ccnt;
    __shared__ float s_sum;

    // ---------- fixup ----------
    if (tid < NM) {
        const float* tg = targets + ((size_t)b * NM + tid) * 5;
        float x1 = tg[0], y1 = tg[1], x2 = tg[2], y2 = tg[3];
        s_tt[tid][0] = x1; s_tt[tid][1] = y1; s_tt[tid][2] = x2; s_tt[tid][3] = y2;
        s_tt[tid][4] = (x2 - x1) * (y2 - y1);
        s_tt[tid][5] = tg[4];
        unsigned long long key = g_bpkey[b * NM + tid];
        s_p[tid] = (int)(0xFFFFFFFFu - (unsigned)(key & 0xFFFFFFFFull));
        s_zero[tid] = 0;
    }
    __syncthreads();
    if (w < NM && lane < NC)
        s_cr[w][lane] = conf[((size_t)b * NP + s_p[w]) * NC + lane];
    __syncthreads();

    if (tid < NM) {
        int j = tid;
        float e0 = 0.f, e1 = 0.f, e2 = 0.f;
#pragma unroll
        for (int c = 0; c < NC; c += 3) {
            e0 += __expf(s_cr[j][c]);
            if (c + 1 < NC) e1 += __expf(s_cr[j][c + 1]);
            if (c + 2 < NC) e2 += __expf(s_cr[j][c + 2]);
        }
        float lse = __logf(e0 + e1 + e2);
        s_lse[j] = lse;
        int cn = (int)(s_tt[j][5] + 1.0f);
        s_cnew[j] = cn;
        s_lcanew[j] = lse - s_cr[j][cn];

        int p = s_p[j];
        float4 pr = __ldg((const float4*)priors + p);
        float bx1 = pr.x - pr.z * 0.5f, by1 = pr.y - pr.w * 0.5f;
        float bx2 = pr.x + pr.z * 0.5f, by2 = pr.y + pr.w * 0.5f;
        float area_b = (bx2 - bx1) * (by2 - by1);
        float bov = -1.f; int bj = 0;
#pragma unroll
        for (int i = 0; i < NM; i++) {
            float ix1 = fmaxf(s_tt[i][0], bx1);
            float iy1 = fmaxf(s_tt[i][1], by1);
            float ix2 = fminf(s_tt[i][2], bx2);
            float iy2 = fminf(s_tt[i][3], by2);
            float iw = fmaxf(ix2 - ix1, 0.f);
            float ih = fmaxf(iy2 - iy1, 0.f);
            float inter = iw * ih;
            float iou = __fdividef(inter, s_tt[i][4] + area_b - inter);
            if (iou > bov) { bov = iou; bj = i; }
        }
        int pos0 = !(bov < 0.5f);
        s_pos0[j] = pos0;
        s_bt0[j] = bj;
        s_cold0[j] = pos0 ? (int)(s_tt[bj][5] + 1.0f) : 0;
    }
    if (tid >= 32 && tid < 32 + 256) {
        int t = tid - 32;
        int i = t >> 4, j = t & 15;
        int p = s_p[j];
        float4 pr = __ldg((const float4*)priors + p);
        float4 ld = __ldg((const float4*)loc + (size_t)b * NP + p);
        s_sl[i][j] = sl1_sum(s_tt[i][0], s_tt[i][1], s_tt[i][2], s_tt[i][3],
                             pr.x, pr.y, pr.z, pr.w, ld);
    }
    __syncthreads();

    if (tid == 0) {
        float d_lossl = 0.f, d_sum = 0.f;
        int d_np = 0;
        for (int j = 0; j < NM; j++) {
            int p = s_p[j];
            int dup = -1;
            for (int i = 0; i < j; i++) if (s_p[i] == p) dup = i;
            int posold, cold, btold;
            if (dup >= 0) { posold = 1; cold = s_cnew[dup]; btold = dup; }
            else { posold = s_pos0[j]; cold = s_cold0[j]; btold = s_bt0[j]; }
            float lca_new = s_lcanew[j];
            float sl_new = s_sl[j][j];
            if (posold) {
                d_sum += lca_new - (s_lse[j] - s_cr[j][cold]);
                d_lossl += sl_new - s_sl[btold][j];
            } else {
                d_np++; d_sum += lca_new; d_lossl += sl_new; s_zero[j] = 1;
            }
        }
        atomicAdd(&g_lossl, d_lossl);
        int npn = g_numpos[b] + d_np;
        g_numpos[b] = npn;
        s_base = g_sumpos[b] + d_sum;
        long long Kl = 3ll * npn;
        s_K = (Kl < (long long)(NP - 1)) ? (int)Kl : (NP - 1);
        s_prefix = 0u; s_krem = (unsigned)((s_K > 0) ? s_K : 0);
        s_sum = 0.f; s_cgt = 0u; s_ccnt = 0u;
    }
    __syncthreads();
    if (tid < NM && s_zero[tid]) g_mined[(size_t)b * NP + s_p[tid]] = 0.f;
    __syncthreads();

    int K = s_K;
    float lossc_b = s_base;

    if (K > 0) {
        // load whole batch into registers (pad 0.0f: mined >= 0)
        const float4* mb4 = (const float4*)(g_mined + (size_t)b * NP);
        unsigned v[NV];
#pragma unroll
        for (int k = 0; k < 6; k++) {
            int i = tid + k * SBLK;
            float4 f = (i < NP / 4) ? mb4[i] : make_float4(0.f, 0.f, 0.f, 0.f);
            v[4 * k + 0] = __float_as_uint(f.x);
            v[4 * k + 1] = __float_as_uint(f.y);
            v[4 * k + 2] = __float_as_uint(f.z);
            v[4 * k + 3] = __float_as_uint(f.w);
        }

        // ---- passes 0,1: full register sweep ----
        for (int pass = 0; pass < 2; pass++) {
            int shift = 24 - 8 * pass;
            for (int i = tid; i < 32 * 257; i += SBLK) hist[i] = 0u;
            __syncthreads();
            unsigned pref = s_prefix;
            unsigned hi = (pref >> shift) >> 8;
#pragma unroll
            for (int k = 0; k < NV; k++) {
                unsigned u = v[k];
                bool a = (((u >> shift) >> 8) == hi);
                unsigned bin = (u >> shift) & 255u;
                unsigned key = a ? bin : 0xFFFFFFFFu;
                unsigned m = __match_any_sync(0xFFFFFFFFu, key);
                if (a && (unsigned)(__ffs(m) - 1) == (unsigned)lane)
                    atomicAdd(&hist[w * 257 + bin], (unsigned)__popc(m));
            }
            __syncthreads();
            if (tid < 256) {
                unsigned s = 0;
#pragma unroll
                for (int w2 = 0; w2 < 32; w2++) s += hist[w2 * 257 + tid];
                s_ssum[tid] = s;
            }
            __syncthreads();
            if (w == 0) {
                unsigned c[8]; unsigned csum = 0;
#pragma unroll
                for (int i = 0; i < 8; i++) { c[i] = s_ssum[lane * 8 + i]; csum += c[i]; }
                unsigned suf = csum;
#pragma unroll
                for (int o = 1; o < 32; o <<= 1) {
                    unsigned x = __shfl_down_sync(0xFFFFFFFFu, suf, o);
                    if (lane + o < 32) suf += x;
                }
                unsigned above = __shfl_down_sync(0xFFFFFFFFu, suf, 1);
                if (lane == 31) above = 0u;
                unsigned kr = s_krem;
                unsigned run = above;
#pragma unroll
                for (int i = 7; i >= 0; i--) {
                    unsigned nr = run + c[i];
                    if (run < kr && nr >= kr) {
                        s_prefix = pref | ((unsigned)(lane * 8 + i) << shift);
                        s_krem = kr - run;
                    }
                    run = nr;
                }
            }
            __syncthreads();
        }

        // ---- compaction sweep: top16 decided; accumulate strictly-greater,
        //      compact equal-top16 candidates to smem ----
        unsigned prefix16 = s_prefix >> 16;
        {
            float gsum = 0.f; unsigned gcnt = 0;
#pragma unroll
            for (int k = 0; k < NV; k++) {
                unsigned u = v[k];
                unsigned t16 = u >> 16;
                if (t16 > prefix16) { gsum += __uint_as_float(u); gcnt++; }
                bool isc = (t16 == prefix16);
                unsigned mask = __ballot_sync(0xFFFFFFFFu, isc);
                if (mask) {
                    int leader = __ffs(mask) - 1;
                    unsigned base = 0;
                    if (isc && lane == leader)
                        base = atomicAdd(&s_ccnt, (unsigned)__popc(mask));
                    base = __shfl_sync(0xFFFFFFFFu, base, leader);
                    if (isc) {
                        unsigned pos = base + (unsigned)__popc(mask & ((1u << lane) - 1u));
                        if (pos < CAP) s_cand[pos] = u;
                    }
                }
            }
#pragma unroll
            for (int o = 16; o > 0; o >>= 1) {
                gsum += __shfl_down_sync(0xFFFFFFFFu, gsum, o);
                gcnt += __shfl_down_sync(0xFFFFFFFFu, gcnt, o);
            }
            if (lane == 0) { atomicAdd(&s_sum, gsum); atomicAdd(&s_cgt, gcnt); }
        }
        __syncthreads();

        unsigned C = s_ccnt;
        bool ovf = (C > CAP);
        int iters = ovf ? 0 : (int)((C + SBLK - 1) / SBLK);

        // ---- passes 2,3 over candidates (or register fallback) ----
        for (int pass = 2; pass < 4; pass++) {
            int shift = 24 - 8 * pass;  // 8, 0
            for (int i = tid; i < 32 * 257; i += SBLK) hist[i] = 0u;
            __syncthreads();
            unsigned pref = s_prefix;
            unsigned hi = (pref >> shift) >> 8;
            if (!ovf) {
                for (int t = 0; t < iters; t++) {
                    int i = tid + t * SBLK;
                    bool in = (i < (int)C);
                    unsigned u = in ? s_cand[i] : 0u;
                    bool a = in && (((u >> shift) >> 8) == hi);
                    unsigned bin = (u >> shift) & 255u;
                    unsigned key = a ? bin : 0xFFFFFFFFu;
                    unsigned m = __match_any_sync(0xFFFFFFFFu, key);
                    if (a && (unsigned)(__ffs(m) - 1) == (unsigned)lane)
                        atomicAdd(&hist[w * 257 + bin], (unsigned)__popc(m));
                }
            } else {
#pragma unroll
                for (int k = 0; k < NV; k++) {
                    unsigned u = v[k];
                    bool a = (((u >> shift) >> 8) == hi);
                    unsigned bin = (u >> shift) & 255u;
                    unsigned key = a ? bin : 0xFFFFFFFFu;
                    unsigned m = __match_any_sync(0xFFFFFFFFu, key);
                    if (a && (unsigned)(__ffs(m) - 1) == (unsigned)lane)
                        atomicAdd(&hist[w * 257 + bin], (unsigned)__popc(m));
                }
            }
            __syncthreads();
            if (tid < 256) {
                unsigned s = 0;
#pragma unroll
                for (int w2 = 0; w2 < 32; w2++) s += hist[w2 * 257 + tid];
                s_ssum[tid] = s;
            }
            __syncthreads();
            if (w == 0) {
                unsigned c[8]; unsigned csum = 0;
#pragma unroll
                for (int i = 0; i < 8; i++) { c[i] = s_ssum[lane * 8 + i]; csum += c[i]; }
                unsigned suf = csum;
#pragma unroll
                for (int o = 1; o < 32; o <<= 1) {
                    unsigned x = __shfl_down_sync(0xFFFFFFFFu, suf, o);
                    if (lane + o < 32) suf += x;
                }
                unsigned above = __shfl_down_sync(0xFFFFFFFFu, suf, 1);
                if (lane == 31) above = 0u;
                unsigned kr = s_krem;
                unsigned run = above;
#pragma unroll
                for (int i = 7; i >= 0; i--) {
                    unsigned nr = run + c[i];
                    if (run < kr && nr >= kr) {
                        s_prefix = pref | ((unsigned)(lane * 8 + i) << shift);
                        s_krem = kr - run;
                    }
                    run = nr;
                }
            }
            __syncthreads();
        }

        // ---- final: sum of values strictly greater than threshold (equal-top16 part) ----
        unsigned tb = s_prefix;
        {
            float lsum = 0.f; unsigned lcnt = 0;
            if (!ovf) {
                for (int t = 0; t < iters; t++) {
                    int i = tid + t * SBLK;
                    if (i < (int)C) {
                        unsigned u = s_cand[i];
                        if (u > tb) { lsum += __uint_as_float(u); lcnt++; }
                    }
                }
            } else {
#pragma unroll
                for (int k = 0; k < NV; k++) {
                    unsigned u = v[k];
                    if ((u >> 16) == prefix16 && u > tb) { lsum += __uint_as_float(u); lcnt++; }
                }
            }
#pragma unroll
            for (int o = 16; o > 0; o >>= 1) {
                lsum += __shfl_down_sync(0xFFFFFFFFu, lsum, o);
                lcnt += __shfl_down_sync(0xFFFFFFFFu, lcnt, o);
            }
            if (lane == 0) { atomicAdd(&s_sum, lsum); atomicAdd(&s_cgt, lcnt); }
        }
        __syncthreads();
        lossc_b = s_base + s_sum + (float)(K - (int)s_cgt) * __uint_as_float(tb);
    }

    // ---------- global accumulate, final output, state reset ----------
    if (tid == 0) {
        atomicAdd(&g_lossc, lossc_b);
        __threadfence();
        s_last = (atomicAdd(&g_done, 1u) == NB - 1);
    }
    __syncthreads();
    if (s_last) {
        if (tid == 0) {
            int n = 0;
            for (int i = 0; i < NB; i++) n += *(volatile int*)&g_numpos[i];
            float fn = (float)n;
            out[0] = *(volatile float*)&g_lossl / fn;
            out[1] = *(volatile float*)&g_lossc / fn;
        }
        __syncthreads();    // out written (reads done) before reset
        g_bpkey[tid] = 0ull;                 // NB*NM == SBLK
        if (tid < NB) { g_numpos[tid] = 0; g_sumpos[tid] = 0.f; }
        if (tid == 0) {
            g_lossl = 0.f; g_lossc = 0.f;
            __threadfence();
            g_done = 0u;
        }
    }
}

extern "C" void kernel_launch(void* const* d_in, const int* in_sizes, int n_in,
                              void* d_out, int out_size)
{
    const float* loc = (const float*)d_in[0];
    const float* conf = (const float*)d_in[1];
    const float* priors = (const float*)d_in[2];
    const float* targets = (const float*)d_in[3];

    dim3 gm(MGX, NB);
    k_main<<<gm, MROWS>>>(loc, conf, priors, targets);
    k_selfix<<<NB, SBLK>>>(loc, conf, priors, targets, (float*)d_out);
}